// round 2
// baseline (speedup 1.0000x reference)
#include <cuda_runtime.h>
#include <cuda_bf16.h>

#define B_ 64
#define S_ 512
#define I_ 512
#define H_ 1024
#define O_ 512

// ---------------------------------------------------------------------------
// Static device scratch (no allocations anywhere)
// ---------------------------------------------------------------------------
__device__ float g_U[(S_ - 1) * B_ * H_];   // U[t][b][j]; later reused as logits[r][o]
__device__ float g_Z[B_ * S_ * H_];         // Z[b][t][j]; t=0 slice stays .bss zero forever
__device__ float g_hbuf[2][B_ * H_];        // ping-pong hidden state
__device__ unsigned g_bar;                  // grid barrier counter

// ---------------------------------------------------------------------------
// f32x2 packed fp32 helpers (sm_100+). FFMA-3reg is half-rate on sm_103a;
// fma.rn.f32x2 performs 2 fp32 MACs per issued instruction.
// ---------------------------------------------------------------------------
static __device__ __forceinline__ void ffma2(unsigned long long& d,
                                             unsigned long long a,
                                             unsigned long long b) {
    asm("fma.rn.f32x2 %0, %1, %2, %0;" : "+l"(d) : "l"(a), "l"(b));
}
static __device__ __forceinline__ unsigned long long pk(float x, float y) {
    unsigned long long r;
    asm("mov.b64 %0, {%1,%2};" : "=l"(r) : "f"(x), "f"(y));
    return r;
}
static __device__ __forceinline__ float2 unpk(unsigned long long v) {
    float2 r;
    asm("mov.b64 {%0,%1}, %2;" : "=f"(r.x), "=f"(r.y) : "l"(v));
    return r;
}

// ---------------------------------------------------------------------------
// Grid barrier: all 128 CTAs resident (1/SM). Monotonic counter, reset by init.
// ---------------------------------------------------------------------------
static __device__ __forceinline__ void gbar(unsigned target) {
    __syncthreads();
    if (threadIdx.x == 0) {
        __threadfence();                     // release prior global writes
        atomicAdd(&g_bar, 1u);
        unsigned v;
        do {
            asm volatile("ld.acquire.gpu.global.u32 %0, [%1];"
                         : "=r"(v) : "l"(&g_bar));
        } while (v < target);
        __threadfence();                     // acquire for the whole block
    }
    __syncthreads();
}

// ---------------------------------------------------------------------------
// Init: h0 -> g_hbuf[0], reset barrier counter
// ---------------------------------------------------------------------------
__global__ void init_k(const float* __restrict__ h0) {
    int i = blockIdx.x * blockDim.x + threadIdx.x;
    if (i < B_ * H_) g_hbuf[0][i] = h0[i];
    if (i == 0) g_bar = 0u;
}

// ---------------------------------------------------------------------------
// Tiled fp32 NT GEMM, 64x64 tile, K-step 16, 256 threads, f32x2 accumulate.
//   MODE 0: U = x[:, t, :] @ Wi^T + bi       (y = t in 0..510, K=512,  N=1024)
//            A row m = batch b;  C[(t*64+b)*H_ + n]
//   MODE 1: logits = Z @ W3^T + b3           (y = row-tile,   K=1024, N=512)
//            A row = g_Z[(y*64+m)*H_];        C[(y*64+m)*O_ + n]
// ---------------------------------------------------------------------------
template <int MODE>
__global__ __launch_bounds__(256) void gemm_k(const float* __restrict__ A,
                                              const float* __restrict__ W,
                                              const float* __restrict__ bias) {
    constexpr int K = (MODE == 0) ? I_ : H_;
    constexpr int N = (MODE == 0) ? H_ : O_;

    __shared__ float As[16][68];
    __shared__ float Ws[16][68];

    const int tid = threadIdx.x;
    const int n0 = blockIdx.x * 64;
    const int y  = blockIdx.y;
    const int lm = tid >> 2;        // 0..63 row for loads
    const int kq = (tid & 3) << 2;  // 0,4,8,12

    const int tx = tid & 15;        // 4-col group
    const int ty = tid >> 4;        // 4-row group

    unsigned long long acc[4][2];
#pragma unroll
    for (int i = 0; i < 4; ++i) { acc[i][0] = 0ull; acc[i][1] = 0ull; }

    for (int k0 = 0; k0 < K; k0 += 16) {
        float4 av;
        if (MODE == 0) {
            // x[b=lm][t=y][k]
            av = *(const float4*)&A[((lm << 9) + y) * I_ + k0 + kq];
        } else {
            av = *(const float4*)&g_Z[((y << 6) + lm) * H_ + k0 + kq];
        }
        float4 wv = *(const float4*)&W[(n0 + lm) * K + k0 + kq];
        As[kq + 0][lm] = av.x; As[kq + 1][lm] = av.y;
        As[kq + 2][lm] = av.z; As[kq + 3][lm] = av.w;
        Ws[kq + 0][lm] = wv.x; Ws[kq + 1][lm] = wv.y;
        Ws[kq + 2][lm] = wv.z; Ws[kq + 3][lm] = wv.w;
        __syncthreads();

#pragma unroll
        for (int kk = 0; kk < 16; ++kk) {
            ulonglong2 a2 = *(const ulonglong2*)&As[kk][ty << 2];
            float4 w4 = *(const float4*)&Ws[kk][tx << 2];
            unsigned long long w0 = pk(w4.x, w4.x);
            unsigned long long w1 = pk(w4.y, w4.y);
            unsigned long long w2 = pk(w4.z, w4.z);
            unsigned long long w3 = pk(w4.w, w4.w);
            ffma2(acc[0][0], a2.x, w0); ffma2(acc[0][1], a2.y, w0);
            ffma2(acc[1][0], a2.x, w1); ffma2(acc[1][1], a2.y, w1);
            ffma2(acc[2][0], a2.x, w2); ffma2(acc[2][1], a2.y, w2);
            ffma2(acc[3][0], a2.x, w3); ffma2(acc[3][1], a2.y, w3);
        }
        __syncthreads();
    }

    const float4 b4 = *(const float4*)&bias[n0 + (tx << 2)];
#pragma unroll
    for (int p = 0; p < 2; ++p) {
        float2 c0 = unpk(acc[0][p]);
        float2 c1 = unpk(acc[1][p]);
        float2 c2 = unpk(acc[2][p]);
        float2 c3 = unpk(acc[3][p]);
        int r_lo = (ty << 2) + (p << 1);      // local rows r_lo, r_lo+1
        float4 o0 = make_float4(c0.x + b4.x, c1.x + b4.y, c2.x + b4.z, c3.x + b4.w);
        float4 o1 = make_float4(c0.y + b4.x, c1.y + b4.y, c2.y + b4.z, c3.y + b4.w);
        long base0 = (long)((y << 6) + r_lo) * N + n0 + (tx << 2);
        *(float4*)&g_U[base0]     = o0;
        *(float4*)&g_U[base0 + N] = o1;
    }
}

// ---------------------------------------------------------------------------
// Persistent recurrence kernel: 128 CTAs (4 b-blocks x 32 j-blocks), 256 thr.
// SMEM: Wh slice [32][1028] (loaded once) + h slice [16][1028] (per step).
// Per step m (0..511): a_m = h_m @ Wh^T + bh on this block;
//   m>=1:  Z[b][m][j]   = tanh(a_m)
//   m<=510: h_{m+1}(b,j) = tanh(U[m](b,j) + a_m)  -> ping-pong buffer
// One grid barrier per step.
// ---------------------------------------------------------------------------
#define WH_STRIDE 1028
#define RECUR_SMEM ((32 * WH_STRIDE + 16 * WH_STRIDE) * 4)

__global__ void __launch_bounds__(256, 1) recur_k(const float* __restrict__ Wh,
                                                  const float* __restrict__ bh) {
    extern __shared__ float sm[];
    float* Whs = sm;                     // [32][WH_STRIDE]
    float* hs  = sm + 32 * WH_STRIDE;    // [16][WH_STRIDE]

    const int tid = threadIdx.x;
    const int c   = blockIdx.x;
    const int j0  = (c & 31) << 5;       // 32 output cols
    const int b0  = (c >> 5) << 4;       // 16 batch rows

    // Load Wh slice once (32 rows x 1024)
    for (int i = tid; i < 32 * 256; i += 256) {
        int row = i >> 8, q = (i & 255) << 2;
        *(float4*)&Whs[row * WH_STRIDE + q] =
            *(const float4*)&Wh[(j0 + row) * H_ + q];
    }

    const int b  = tid >> 4;             // 0..15
    const int jj = tid & 15;             // 0..15 -> cols jj and jj+16
    const float bhA = bh[j0 + jj];
    const float bhB = bh[j0 + jj + 16];
    const float* wA = &Whs[jj * WH_STRIDE];
    const float* wB = &Whs[(jj + 16) * WH_STRIDE];
    const float* hrow = &hs[b * WH_STRIDE];
    const int gr = b0 + b;               // global batch row

    for (int m = 0; m < S_; ++m) {
        // stage h_m slice for this b-block
        const float* hsrc = g_hbuf[m & 1] + (b0 << 10);
        for (int i = tid; i < 16 * 256; i += 256) {
            int row = i >> 8, q = (i & 255) << 2;
            *(float4*)&hs[row * WH_STRIDE + q] =
                *(const float4*)&hsrc[(row << 10) + q];
        }
        __syncthreads();

        unsigned long long aA0 = 0ull, aA1 = 0ull, aB0 = 0ull, aB1 = 0ull;
#pragma unroll 8
        for (int k = 0; k < H_; k += 4) {
            ulonglong2 h2 = *(const ulonglong2*)&hrow[k];
            ulonglong2 wa = *(const ulonglong2*)&wA[k];
            ulonglong2 wb = *(const ulonglong2*)&wB[k];
            ffma2(aA0, h2.x, wa.x); ffma2(aA1, h2.y, wa.y);
            ffma2(aB0, h2.x, wb.x); ffma2(aB1, h2.y, wb.y);
        }
        float2 a0 = unpk(aA0), a1 = unpk(aA1);
        float2 bb0 = unpk(aB0), bb1 = unpk(aB1);
        float fA = (a0.x + a0.y) + (a1.x + a1.y) + bhA;
        float fB = (bb0.x + bb0.y) + (bb1.x + bb1.y) + bhB;

        if (m >= 1) {
            long zb = ((long)gr * S_ + m) * H_ + j0 + jj;
            g_Z[zb]      = tanhf(fA);
            g_Z[zb + 16] = tanhf(fB);
        }
        if (m <= S_ - 2) {
            long ub = ((long)m * 64 + gr) * H_ + j0 + jj;
            float hA = tanhf(g_U[ub] + fA);
            float hB = tanhf(g_U[ub + 16] + fB);
            float* hdst = g_hbuf[(m + 1) & 1];
            hdst[gr * H_ + j0 + jj]      = hA;
            hdst[gr * H_ + j0 + jj + 16] = hB;
        }
        if (m != S_ - 1) gbar((unsigned)(128 * (m + 1)));
    }
}

// ---------------------------------------------------------------------------
// Row softmax over O_=512 cols; warp per row, logits read from g_U (reused).
// ---------------------------------------------------------------------------
__global__ __launch_bounds__(256) void softmax_k(float* __restrict__ out) {
    int r = blockIdx.x * 8 + (threadIdx.x >> 5);
    int l = threadIdx.x & 31;
    const float* row = g_U + (long)r * O_;

    float4 v[4];
    float mx = -3.0e38f;
#pragma unroll
    for (int q = 0; q < 4; ++q) {
        v[q] = *(const float4*)&row[(l + (q << 5)) << 2];
        mx = fmaxf(mx, fmaxf(fmaxf(v[q].x, v[q].y), fmaxf(v[q].z, v[q].w)));
    }
#pragma unroll
    for (int o = 16; o; o >>= 1) mx = fmaxf(mx, __shfl_xor_sync(~0u, mx, o));

    float s = 0.f;
#pragma unroll
    for (int q = 0; q < 4; ++q) {
        v[q].x = expf(v[q].x - mx); v[q].y = expf(v[q].y - mx);
        v[q].z = expf(v[q].z - mx); v[q].w = expf(v[q].w - mx);
        s += (v[q].x + v[q].y) + (v[q].z + v[q].w);
    }
#pragma unroll
    for (int o = 16; o; o >>= 1) s += __shfl_xor_sync(~0u, s, o);
    float inv = 1.0f / s;

#pragma unroll
    for (int q = 0; q < 4; ++q) {
        float4 w = make_float4(v[q].x * inv, v[q].y * inv, v[q].z * inv, v[q].w * inv);
        *(float4*)&out[(long)r * O_ + ((l + (q << 5)) << 2)] = w;
    }
}

__global__ void copyht_k(float* __restrict__ dst) {
    int i = blockIdx.x * blockDim.x + threadIdx.x;
    if (i < B_ * H_) dst[i] = g_hbuf[1][i];
}

// ---------------------------------------------------------------------------
// Launch
// ---------------------------------------------------------------------------
extern "C" void kernel_launch(void* const* d_in, const int* in_sizes, int n_in,
                              void* d_out, int out_size) {
    const float* x  = (const float*)d_in[0];
    const float* h0 = (const float*)d_in[1];
    const float* Wi = (const float*)d_in[2];
    const float* bi = (const float*)d_in[3];
    const float* Wh = (const float*)d_in[4];
    const float* bh = (const float*)d_in[5];
    const float* W3 = (const float*)d_in[6];
    const float* b3 = (const float*)d_in[7];
    float* out = (float*)d_out;

    cudaFuncSetAttribute(recur_k, cudaFuncAttributeMaxDynamicSharedMemorySize,
                         RECUR_SMEM);

    // 1. h0 -> state, barrier reset
    init_k<<<(B_ * H_ + 255) / 256, 256>>>(h0);

    // 2. U[t][b][:] = x[b][t][:] @ Wi^T + bi   (t = 0..510)
    gemm_k<0><<<dim3(H_ / 64, S_ - 1), 256>>>(x, Wi, bi);

    // 3. Serial recurrence (persistent, 128 CTAs, 512 steps)
    recur_k<<<128, 256, RECUR_SMEM>>>(Wh, bh);

    // 4. logits = Z @ W3^T + b3   (writes g_U, reused as logits buffer)
    gemm_k<1><<<dim3(O_ / 64, (B_ * S_) / 64), 256>>>(nullptr, W3, b3);

    // 5. softmax -> d_out
    softmax_k<<<(B_ * S_) / 8, 256>>>(out);

    // 6. final hidden state appended after softmax output
    if (out_size >= B_ * S_ * O_ + B_ * H_) {
        copyht_k<<<(B_ * H_ + 255) / 256, 256>>>(out + (long)B_ * S_ * O_);
    }
}

// round 3
// speedup vs baseline: 1.5359x; 1.5359x over previous
#include <cuda_runtime.h>
#include <cuda_bf16.h>

#define B_ 64
#define S_ 512
#define I_ 512
#define H_ 1024
#define O_ 512

// ---------------------------------------------------------------------------
// Static device scratch (no allocations anywhere)
// ---------------------------------------------------------------------------
__device__ float g_U[(S_ - 1) * B_ * H_];   // U[t][b][j]; later reused as logits[r][o]
__device__ float g_Z[B_ * S_ * H_];         // Z[b][t][j]; t=0 slice stays .bss zero forever
__device__ float g_hbuf[2][B_ * H_];        // ping-pong hidden state
__device__ unsigned g_bar;                  // grid barrier counter

// ---------------------------------------------------------------------------
// f32x2 packed fp32 helpers (sm_100+): 2 fp32 MACs per issued instruction.
// ---------------------------------------------------------------------------
static __device__ __forceinline__ void ffma2(unsigned long long& d,
                                             unsigned long long a,
                                             unsigned long long b) {
    asm("fma.rn.f32x2 %0, %1, %2, %0;" : "+l"(d) : "l"(a), "l"(b));
}
static __device__ __forceinline__ unsigned long long pk(float x, float y) {
    unsigned long long r;
    asm("mov.b64 %0, {%1,%2};" : "=l"(r) : "f"(x), "f"(y));
    return r;
}
static __device__ __forceinline__ float2 unpk(unsigned long long v) {
    float2 r;
    asm("mov.b64 {%0,%1}, %2;" : "=f"(r.x), "=f"(r.y) : "l"(v));
    return r;
}

// ---------------------------------------------------------------------------
// Grid barrier: all 128 CTAs resident (1/SM). Monotonic counter, reset by init.
// ---------------------------------------------------------------------------
static __device__ __forceinline__ void gbar(unsigned target) {
    __syncthreads();
    if (threadIdx.x == 0) {
        __threadfence();                     // release prior global writes
        atomicAdd(&g_bar, 1u);
        unsigned v;
        do {
            asm volatile("ld.acquire.gpu.global.u32 %0, [%1];"
                         : "=r"(v) : "l"(&g_bar));
        } while (v < target);
        __threadfence();                     // acquire for the whole block
    }
    __syncthreads();
}

// ---------------------------------------------------------------------------
// Init: h0 -> g_hbuf[0], reset barrier counter
// ---------------------------------------------------------------------------
__global__ void init_k(const float* __restrict__ h0) {
    int i = blockIdx.x * blockDim.x + threadIdx.x;
    if (i < B_ * H_) g_hbuf[0][i] = h0[i];
    if (i == 0) g_bar = 0u;
}

// ---------------------------------------------------------------------------
// Tiled fp32 NT GEMM, 64x64 tile, K-step 16, 256 threads, f32x2 accumulate.
//   MODE 0: U = x[:, t, :] @ Wi^T + bi       (y = t in 0..510, K=512,  N=1024)
//   MODE 1: logits = Z @ W3^T + b3           (y = row-tile,   K=1024, N=512)
// ---------------------------------------------------------------------------
template <int MODE>
__global__ __launch_bounds__(256) void gemm_k(const float* __restrict__ A,
                                              const float* __restrict__ W,
                                              const float* __restrict__ bias) {
    constexpr int K = (MODE == 0) ? I_ : H_;
    constexpr int N = (MODE == 0) ? H_ : O_;

    __shared__ float As[16][68];
    __shared__ float Ws[16][68];

    const int tid = threadIdx.x;
    const int n0 = blockIdx.x * 64;
    const int y  = blockIdx.y;
    const int lm = tid >> 2;        // 0..63 row for loads
    const int kq = (tid & 3) << 2;  // 0,4,8,12

    const int tx = tid & 15;        // 4-col group
    const int ty = tid >> 4;        // 4-row group

    unsigned long long acc[4][2];
#pragma unroll
    for (int i = 0; i < 4; ++i) { acc[i][0] = 0ull; acc[i][1] = 0ull; }

    for (int k0 = 0; k0 < K; k0 += 16) {
        float4 av;
        if (MODE == 0) {
            av = *(const float4*)&A[((lm << 9) + y) * I_ + k0 + kq];
        } else {
            av = *(const float4*)&g_Z[((y << 6) + lm) * H_ + k0 + kq];
        }
        float4 wv = *(const float4*)&W[(n0 + lm) * K + k0 + kq];
        As[kq + 0][lm] = av.x; As[kq + 1][lm] = av.y;
        As[kq + 2][lm] = av.z; As[kq + 3][lm] = av.w;
        Ws[kq + 0][lm] = wv.x; Ws[kq + 1][lm] = wv.y;
        Ws[kq + 2][lm] = wv.z; Ws[kq + 3][lm] = wv.w;
        __syncthreads();

#pragma unroll
        for (int kk = 0; kk < 16; ++kk) {
            ulonglong2 a2 = *(const ulonglong2*)&As[kk][ty << 2];
            float4 w4 = *(const float4*)&Ws[kk][tx << 2];
            unsigned long long w0 = pk(w4.x, w4.x);
            unsigned long long w1 = pk(w4.y, w4.y);
            unsigned long long w2 = pk(w4.z, w4.z);
            unsigned long long w3 = pk(w4.w, w4.w);
            ffma2(acc[0][0], a2.x, w0); ffma2(acc[0][1], a2.y, w0);
            ffma2(acc[1][0], a2.x, w1); ffma2(acc[1][1], a2.y, w1);
            ffma2(acc[2][0], a2.x, w2); ffma2(acc[2][1], a2.y, w2);
            ffma2(acc[3][0], a2.x, w3); ffma2(acc[3][1], a2.y, w3);
        }
        __syncthreads();
    }

    const float4 b4 = *(const float4*)&bias[n0 + (tx << 2)];
#pragma unroll
    for (int p = 0; p < 2; ++p) {
        float2 c0 = unpk(acc[0][p]);
        float2 c1 = unpk(acc[1][p]);
        float2 c2 = unpk(acc[2][p]);
        float2 c3 = unpk(acc[3][p]);
        int r_lo = (ty << 2) + (p << 1);
        float4 o0 = make_float4(c0.x + b4.x, c1.x + b4.y, c2.x + b4.z, c3.x + b4.w);
        float4 o1 = make_float4(c0.y + b4.x, c1.y + b4.y, c2.y + b4.z, c3.y + b4.w);
        long base0 = (long)((y << 6) + r_lo) * N + n0 + (tx << 2);
        *(float4*)&g_U[base0]     = o0;
        *(float4*)&g_U[base0 + N] = o1;
    }
}

// ---------------------------------------------------------------------------
// Persistent recurrence kernel v2: register-resident Wh + broadcast LDS.
// 128 CTAs = 4 b-groups (16 b) x 32 j-groups (32 j). 256 threads = 8 warps.
// warp w owns k-slice [w*128, w*128+128); lane l owns j = j0 + l.
// Each thread keeps Wh[j][k-slice] in 64 f32x2 registers for all 512 steps.
// Per step: stage h (64KB, coalesced LDG->STS), per-b dot products with
// broadcast LDS.128 (all lanes same address -> N=1), split-k partials to
// SMEM, reduce + bias + tanh + fused z/h writes, one grid barrier.
// ---------------------------------------------------------------------------
#define RECUR_SMEM ((16 * 1024 + 8 * 16 * 32) * 4)   /* 64KB h + 16KB partials */

__global__ void __launch_bounds__(256, 1) recur_k(const float* __restrict__ Wh,
                                                  const float* __restrict__ bh) {
    extern __shared__ float sm[];
    float* hs   = sm;              // [16][1024]
    float* part = sm + 16 * 1024;  // [8][16][32]

    const int tid = threadIdx.x;
    const int w   = tid >> 5;            // warp id 0..7 -> k slice
    const int l   = tid & 31;            // lane -> j
    const int cb  = blockIdx.x;
    const int j0  = (cb & 31) << 5;      // 32 j per CTA
    const int b0  = (cb >> 5) << 4;      // 16 b per CTA
    const int j   = j0 + l;
    const int kw  = w << 7;              // k offset 0,128,...,896

    // Wh[j][kw..kw+127] -> 64 f32x2 registers (held for the whole kernel)
    unsigned long long wreg[64];
    {
        const float* src = &Wh[j * H_ + kw];
#pragma unroll
        for (int q = 0; q < 32; ++q) {
            float4 v = *(const float4*)&src[q << 2];
            wreg[2 * q]     = pk(v.x, v.y);
            wreg[2 * q + 1] = pk(v.z, v.w);
        }
    }
    const float bhj = bh[j];

    const int rb = tid >> 5;             // reduce-phase batch row (0..7)
    const int gb0 = b0 + rb, gb1 = b0 + rb + 8;

    for (int m = 0; m < S_; ++m) {
        // ---- stage h_m slice (16 x 1024 contiguous floats) ----
        const float* hsrc = g_hbuf[m & 1] + (b0 << 10);
        for (int i = tid; i < 4096; i += 256) {
            *(float4*)&hs[i << 2] = *(const float4*)&hsrc[i << 2];
        }
        // prefetch U[m] for this thread's two outputs (consumed after reduce)
        float u0 = 0.f, u1 = 0.f;
        if (m <= S_ - 2) {
            u0 = g_U[((long)m * 64 + gb0) * H_ + j];
            u1 = g_U[((long)m * 64 + gb1) * H_ + j];
        }
        __syncthreads();

        // ---- split-k partials: per b, 32 broadcast LDS.128 + 64 FFMA2 ----
        for (int b = 0; b < 16; ++b) {
            const float* hrow = &hs[(b << 10) + kw];
            unsigned long long a0 = 0ull, a1 = 0ull, a2 = 0ull, a3 = 0ull;
#pragma unroll
            for (int q = 0; q < 16; ++q) {
                ulonglong2 h01 = *(const ulonglong2*)&hrow[q << 3];
                ulonglong2 h23 = *(const ulonglong2*)&hrow[(q << 3) + 4];
                ffma2(a0, h01.x, wreg[4 * q]);
                ffma2(a1, h01.y, wreg[4 * q + 1]);
                ffma2(a2, h23.x, wreg[4 * q + 2]);
                ffma2(a3, h23.y, wreg[4 * q + 3]);
            }
            float2 f0 = unpk(a0), f1 = unpk(a1), f2 = unpk(a2), f3 = unpk(a3);
            part[(w << 9) + (b << 5) + l] =
                ((f0.x + f0.y) + (f1.x + f1.y)) + ((f2.x + f2.y) + (f3.x + f3.y));
        }
        __syncthreads();

        // ---- reduce 8 partials, bias, tanh, fused z/h writes ----
        {
            float s0 = 0.f, s1 = 0.f;
#pragma unroll
            for (int ww = 0; ww < 8; ++ww) {
                s0 += part[(ww << 9) + (rb << 5) + l];
                s1 += part[(ww << 9) + ((rb + 8) << 5) + l];
            }
            float av0 = s0 + bhj;
            float av1 = s1 + bhj;
            if (m >= 1) {
                g_Z[((long)gb0 * S_ + m) * H_ + j] = tanhf(av0);
                g_Z[((long)gb1 * S_ + m) * H_ + j] = tanhf(av1);
            }
            if (m <= S_ - 2) {
                float* hd = g_hbuf[(m + 1) & 1];
                hd[gb0 * H_ + j] = tanhf(u0 + av0);
                hd[gb1 * H_ + j] = tanhf(u1 + av1);
            }
        }
        if (m != S_ - 1) gbar((unsigned)(128 * (m + 1)));
    }
}

// ---------------------------------------------------------------------------
// Row softmax over O_=512 cols; warp per row, logits read from g_U (reused).
// ---------------------------------------------------------------------------
__global__ __launch_bounds__(256) void softmax_k(float* __restrict__ out) {
    int r = blockIdx.x * 8 + (threadIdx.x >> 5);
    int l = threadIdx.x & 31;
    const float* row = g_U + (long)r * O_;

    float4 v[4];
    float mx = -3.0e38f;
#pragma unroll
    for (int q = 0; q < 4; ++q) {
        v[q] = *(const float4*)&row[(l + (q << 5)) << 2];
        mx = fmaxf(mx, fmaxf(fmaxf(v[q].x, v[q].y), fmaxf(v[q].z, v[q].w)));
    }
#pragma unroll
    for (int o = 16; o; o >>= 1) mx = fmaxf(mx, __shfl_xor_sync(~0u, mx, o));

    float s = 0.f;
#pragma unroll
    for (int q = 0; q < 4; ++q) {
        v[q].x = expf(v[q].x - mx); v[q].y = expf(v[q].y - mx);
        v[q].z = expf(v[q].z - mx); v[q].w = expf(v[q].w - mx);
        s += (v[q].x + v[q].y) + (v[q].z + v[q].w);
    }
#pragma unroll
    for (int o = 16; o; o >>= 1) s += __shfl_xor_sync(~0u, s, o);
    float inv = 1.0f / s;

#pragma unroll
    for (int q = 0; q < 4; ++q) {
        float4 wv = make_float4(v[q].x * inv, v[q].y * inv, v[q].z * inv, v[q].w * inv);
        *(float4*)&out[(long)r * O_ + ((l + (q << 5)) << 2)] = wv;
    }
}

__global__ void copyht_k(float* __restrict__ dst) {
    int i = blockIdx.x * blockDim.x + threadIdx.x;
    if (i < B_ * H_) dst[i] = g_hbuf[1][i];
}

// ---------------------------------------------------------------------------
// Launch
// ---------------------------------------------------------------------------
extern "C" void kernel_launch(void* const* d_in, const int* in_sizes, int n_in,
                              void* d_out, int out_size) {
    const float* x  = (const float*)d_in[0];
    const float* h0 = (const float*)d_in[1];
    const float* Wi = (const float*)d_in[2];
    const float* bi = (const float*)d_in[3];
    const float* Wh = (const float*)d_in[4];
    const float* bh = (const float*)d_in[5];
    const float* W3 = (const float*)d_in[6];
    const float* b3 = (const float*)d_in[7];
    float* out = (float*)d_out;

    cudaFuncSetAttribute(recur_k, cudaFuncAttributeMaxDynamicSharedMemorySize,
                         RECUR_SMEM);

    // 1. h0 -> state, barrier reset
    init_k<<<(B_ * H_ + 255) / 256, 256>>>(h0);

    // 2. U[t][b][:] = x[b][t][:] @ Wi^T + bi   (t = 0..510)
    gemm_k<0><<<dim3(H_ / 64, S_ - 1), 256>>>(x, Wi, bi);

    // 3. Serial recurrence (persistent, 128 CTAs, 512 steps)
    recur_k<<<128, 256, RECUR_SMEM>>>(Wh, bh);

    // 4. logits = Z @ W3^T + b3   (writes g_U, reused as logits buffer)
    gemm_k<1><<<dim3(O_ / 64, (B_ * S_) / 64), 256>>>(nullptr, W3, b3);

    // 5. softmax -> d_out
    softmax_k<<<(B_ * S_) / 8, 256>>>(out);

    // 6. final hidden state appended after softmax output
    if (out_size >= B_ * S_ * O_ + B_ * H_) {
        copyht_k<<<(B_ * H_ + 255) / 256, 256>>>(out + (long)B_ * S_ * O_);
    }
}